// round 6
// baseline (speedup 1.0000x reference)
#include <cuda_runtime.h>
#include <cstdint>

// Wilson-Cowan, N=2^20, 100 serial steps.
// R6: hybrid pipe-split (3 pairs tanh.approx.f32 on MUFU, 1 pair MUFU-free
//     exp-sigmoid on FMA/ALU) as R5, with the exp-path reciprocal upgraded:
//       - shared reciprocal: r = 1/(wE*wI) with magic seed + TWO Newton steps
//         (err ~1.4e-6 vs R5's Newton-1 2.6e-3 that put rel_err at 9.7e-4)
//       - sigma_E = r*wI, sigma_I = r*wE
//     Net: 2 fewer fma2 per exp pair-step AND ~200x lower sigma error.
//
// Folding (gain=1, threshold=4, dt=0.1):
//   tanh path: sigmoid(x-4) = 0.5 + 0.5*tanh(0.5*(x-4))
//   exp  path: sigma = 1/(1 + 2^s), s = log2(e)*(4 - input)
//   E' = 0.99E + 0.01*sigma_E ; I' = 0.98I + 0.02*sigma_I
// Convex combination keeps state in [0,1] in-loop; exact clip once at end.

typedef unsigned long long u64;

__device__ __forceinline__ u64 pack2(float lo, float hi) {
    u64 r; asm("mov.b64 %0, {%1, %2};" : "=l"(r) : "f"(lo), "f"(hi)); return r;
}
__device__ __forceinline__ void unpack2(float& lo, float& hi, u64 v) {
    asm("mov.b64 {%0, %1}, %2;" : "=f"(lo), "=f"(hi) : "l"(v));
}
__device__ __forceinline__ u64 fma2(u64 a, u64 b, u64 c) {
    u64 d; asm("fma.rn.f32x2 %0, %1, %2, %3;" : "=l"(d) : "l"(a), "l"(b), "l"(c)); return d;
}
__device__ __forceinline__ u64 add2(u64 a, u64 b) {
    u64 d; asm("add.rn.f32x2 %0, %1, %2;" : "=l"(d) : "l"(a), "l"(b)); return d;
}
__device__ __forceinline__ u64 mul2(u64 a, u64 b) {
    u64 d; asm("mul.rn.f32x2 %0, %1, %2;" : "=l"(d) : "l"(a), "l"(b)); return d;
}
__device__ __forceinline__ float tanhf_a(float x) {
    float r; asm("tanh.approx.f32 %0, %1;" : "=f"(r) : "f"(x)); return r;
}

// packed z = 2^s via magic-add range reduction + deg-4 Taylor + int exponent
// splice. s in [-13, 22] here -> all intermediates normal floats.
__device__ __forceinline__ u64 exp2_2(u64 s2,
                                      u64 MAG, u64 NMAG, u64 NEG1, u64 ONE,
                                      u64 A4, u64 A3, u64 A2, u64 A1)
{
    u64 m2 = add2(s2, MAG);            // low bits hold rint(s)
    u64 d2 = add2(m2, NMAG);           // float(rint(s)), exact
    u64 f2 = fma2(d2, NEG1, s2);       // f = s - rint(s) in [-0.5, 0.5]
    u64 p  = fma2(A4, f2, A3);         // 2^f Taylor deg-4 (rel err ~4e-5)
    p = fma2(p, f2, A2);
    p = fma2(p, f2, A1);
    p = fma2(p, f2, ONE);
    float mlo, mhi, plo, phi;
    unpack2(mlo, mhi, m2);
    unpack2(plo, phi, p);
    int zlo = __float_as_int(plo) + (__float_as_int(mlo) << 23);
    int zhi = __float_as_int(phi) + (__float_as_int(mhi) << 23);
    return pack2(__int_as_float(zlo), __int_as_float(zhi));
}

#define LOG2E 1.4426950408889634f

__global__ __launch_bounds__(128, 7)
void wilson_cowan_kernel(const float4* __restrict__ E0,
                         const float4* __restrict__ I0,
                         const float4* __restrict__ IextE,
                         const float4* __restrict__ IextI,
                         const int*    __restrict__ steps_ptr,
                         float* __restrict__ out,
                         int n, int n4, int out_size)
{
    int i = blockIdx.x * blockDim.x + threadIdx.x;
    const int stride = n4 / 2;

    if (blockIdx.x == 0 && threadIdx.x == 0) {
        for (int k = 2 * n; k < out_size; ++k) out[k] = 0.0f;
    }
    if (i >= stride) return;

    const int steps = steps_ptr ? __ldg(steps_ptr) : 100;

    float4 e4[2]  = { E0[i],    E0[i + stride] };
    float4 i4[2]  = { I0[i],    I0[i + stride] };
    float4 xe4[2] = { IextE[i], IextE[i + stride] };
    float4 xi4[2] = { IextI[i], IextI[i + stride] };

    u64 E2[4], I2[4];
    u64 cE2[3], cI2[3];     // tanh path: 0.5*(Iext-4)
    u64 sE0, sI0;           // exp path:  L*(4-Iext)
    {
        const float* e[2]  = { &e4[0].x,  &e4[1].x };
        const float* ii[2] = { &i4[0].x,  &i4[1].x };
        const float* xe[2] = { &xe4[0].x, &xe4[1].x };
        const float* xi[2] = { &xi4[0].x, &xi4[1].x };
        #pragma unroll
        for (int p = 0; p < 4; ++p) {
            int q = p >> 1, h = p & 1;
            E2[p] = pack2(e[q][2*h],  e[q][2*h+1]);
            I2[p] = pack2(ii[q][2*h], ii[q][2*h+1]);
            if (p < 3) {
                cE2[p] = pack2(0.5f*(xe[q][2*h]-4.0f), 0.5f*(xe[q][2*h+1]-4.0f));
                cI2[p] = pack2(0.5f*(xi[q][2*h]-4.0f), 0.5f*(xi[q][2*h+1]-4.0f));
            } else {
                sE0 = pack2(LOG2E*(4.0f-xe[q][2*h]), LOG2E*(4.0f-xe[q][2*h+1]));
                sI0 = pack2(LOG2E*(4.0f-xi[q][2*h]), LOG2E*(4.0f-xi[q][2*h+1]));
            }
        }
    }

    const u64 AEE = pack2( 6.0f,  6.0f);
    const u64 AEI = pack2(-2.0f, -2.0f);
    const u64 AIE = pack2( 6.5f,  6.5f);
    const u64 AII = pack2(-5.5f, -5.5f);
    const u64 ME  = pack2(0.99f, 0.99f);
    const u64 BE  = pack2(0.005f, 0.005f);
    const u64 MI  = pack2(0.98f, 0.98f);
    const u64 BI  = pack2(0.01f, 0.01f);
    const u64 XEE = pack2(-12.0f*LOG2E, -12.0f*LOG2E);
    const u64 XEI = pack2(  4.0f*LOG2E,   4.0f*LOG2E);
    const u64 XIE = pack2(-13.0f*LOG2E, -13.0f*LOG2E);
    const u64 XII = pack2( 11.0f*LOG2E,  11.0f*LOG2E);
    const u64 KE  = pack2(0.01f, 0.01f);
    const u64 KI  = pack2(0.02f, 0.02f);
    const u64 MAG  = pack2( 12582912.0f,  12582912.0f);   // 1.5*2^23
    const u64 NMAG = pack2(-12582912.0f, -12582912.0f);
    const u64 NEG1 = pack2(-1.0f, -1.0f);
    const u64 ONE  = pack2( 1.0f,  1.0f);
    const u64 A1 = pack2(0.69314718f, 0.69314718f);
    const u64 A2 = pack2(0.24022651f, 0.24022651f);
    const u64 A3 = pack2(0.05550411f, 0.05550411f);
    const u64 A4 = pack2(0.00961813f, 0.00961813f);

    for (int s = 0; s < steps; ++s) {
        // ---- pairs 0-2: MUFU (scalar tanh) path ----
        #pragma unroll
        for (int p = 0; p < 3; ++p) {
            u64 yE = fma2(AEE, E2[p], fma2(AEI, I2[p], cE2[p]));
            u64 yI = fma2(AIE, E2[p], fma2(AII, I2[p], cI2[p]));
            float a, b, c, d;
            unpack2(a, b, yE);
            unpack2(c, d, yI);
            u64 tE = pack2(tanhf_a(a), tanhf_a(b));
            u64 tI = pack2(tanhf_a(c), tanhf_a(d));
            E2[p] = fma2(BE, tE, fma2(ME, E2[p], BE));
            I2[p] = fma2(BI, tI, fma2(MI, I2[p], BI));
        }
        // ---- pair 3: FMA/ALU path, shared Newton-2 reciprocal ----
        {
            u64 sE = fma2(XEE, E2[3], fma2(XEI, I2[3], sE0));
            u64 sI = fma2(XIE, E2[3], fma2(XII, I2[3], sI0));
            u64 zE = exp2_2(sE, MAG, NMAG, NEG1, ONE, A4, A3, A2, A1);
            u64 zI = exp2_2(sI, MAG, NMAG, NEG1, ONE, A4, A3, A2, A1);
            u64 wE = add2(zE, ONE);        // in [1+2^-11.5, ~2900]
            u64 wI = add2(zI, ONE);        // in [1+2^-13,  ~3.2e6]
            u64 P  = mul2(wE, wI);         // <= ~1e10, normal
            u64 nP = mul2(P, NEG1);
            float plo, phi;
            unpack2(plo, phi, P);
            u64 r = pack2(__int_as_float(0x7EF311C3 - __float_as_int(plo)),
                          __int_as_float(0x7EF311C3 - __float_as_int(phi)));
            r = fma2(r, fma2(nP, r, ONE), r);   // Newton 1
            r = fma2(r, fma2(nP, r, ONE), r);   // Newton 2: rel err ~1e-6
            u64 gE = mul2(r, wI);          // 1/wE
            u64 gI = mul2(r, wE);          // 1/wI
            E2[3] = fma2(KE, gE, mul2(ME, E2[3]));
            I2[3] = fma2(KI, gI, mul2(MI, I2[3]));
        }
    }

    #pragma unroll
    for (int q = 0; q < 2; ++q) {
        float4 eo, io;
        unpack2(eo.x, eo.y, E2[q*2]); unpack2(eo.z, eo.w, E2[q*2+1]);
        unpack2(io.x, io.y, I2[q*2]); unpack2(io.z, io.w, I2[q*2+1]);
        eo.x = __saturatef(eo.x); eo.y = __saturatef(eo.y);
        eo.z = __saturatef(eo.z); eo.w = __saturatef(eo.w);
        io.x = __saturatef(io.x); io.y = __saturatef(io.y);
        io.z = __saturatef(io.z); io.w = __saturatef(io.w);
        int idx = i + q * stride;
        reinterpret_cast<float4*>(out)[idx]     = eo;
        reinterpret_cast<float4*>(out + n)[idx] = io;
    }
}

extern "C" void kernel_launch(void* const* d_in, const int* in_sizes, int n_in,
                              void* d_out, int out_size)
{
    const float4* E0    = (const float4*)d_in[0];
    const float4* I0    = (const float4*)d_in[1];
    const float4* IextE = (const float4*)d_in[2];
    const float4* IextI = (const float4*)d_in[3];
    const int* steps_ptr = (n_in >= 5) ? (const int*)d_in[4] : nullptr;

    int n = in_sizes[0];
    int n4 = n / 4;
    int work = n4 / 2;                 // 8 elems per thread
    int threads = 128;
    int blocks = (work + threads - 1) / threads;   // 1024

    wilson_cowan_kernel<<<blocks, threads>>>(E0, I0, IextE, IextI, steps_ptr,
                                             (float*)d_out, n, n4, out_size);
}

// round 7
// speedup vs baseline: 1.0485x; 1.0485x over previous
#include <cuda_runtime.h>
#include <cstdint>

// Wilson-Cowan, N=2^20, 100 serial steps.
// R7: pipe-balanced hybrid. Lane-rate model (fitted over R1-R6):
//   FMA pipe: 32 lanes/cyc/SMSP (FFMA2 rt2); MUFU: 4 tanh-lanes/cyc/SMSP.
//   tanh path: (8 FMA, 2 MUFU) lanes/elem-step; exp path: (31, 0).
//   Optimal exp fraction x = 0.84 -> pair 3 dithers 5 exp-steps : 1 tanh-step
//   (100 = 16*6 + 4 exp remainder -> f = 0.84 exactly). Newton negation via
//   sign-bit XOR on the idle ALU pipe (saves 1 mul2/exp-step).

typedef unsigned long long u64;

__device__ __forceinline__ u64 pack2(float lo, float hi) {
    u64 r; asm("mov.b64 %0, {%1, %2};" : "=l"(r) : "f"(lo), "f"(hi)); return r;
}
__device__ __forceinline__ void unpack2(float& lo, float& hi, u64 v) {
    asm("mov.b64 {%0, %1}, %2;" : "=f"(lo), "=f"(hi) : "l"(v));
}
__device__ __forceinline__ u64 fma2(u64 a, u64 b, u64 c) {
    u64 d; asm("fma.rn.f32x2 %0, %1, %2, %3;" : "=l"(d) : "l"(a), "l"(b), "l"(c)); return d;
}
__device__ __forceinline__ u64 add2(u64 a, u64 b) {
    u64 d; asm("add.rn.f32x2 %0, %1, %2;" : "=l"(d) : "l"(a), "l"(b)); return d;
}
__device__ __forceinline__ u64 mul2(u64 a, u64 b) {
    u64 d; asm("mul.rn.f32x2 %0, %1, %2;" : "=l"(d) : "l"(a), "l"(b)); return d;
}
__device__ __forceinline__ float tanhf_a(float x) {
    float r; asm("tanh.approx.f32 %0, %1;" : "=f"(r) : "f"(x)); return r;
}

#define LOG2E 1.4426950408889634f
#define SIGN2 0x8000000080000000ULL

__global__ __launch_bounds__(128, 7)
void wilson_cowan_kernel(const float4* __restrict__ E0,
                         const float4* __restrict__ I0,
                         const float4* __restrict__ IextE,
                         const float4* __restrict__ IextI,
                         const int*    __restrict__ steps_ptr,
                         float* __restrict__ out,
                         int n, int n4, int out_size)
{
    int i = blockIdx.x * blockDim.x + threadIdx.x;
    const int stride = n4 / 2;

    if (blockIdx.x == 0 && threadIdx.x == 0) {
        for (int k = 2 * n; k < out_size; ++k) out[k] = 0.0f;
    }
    if (i >= stride) return;

    const int steps = steps_ptr ? __ldg(steps_ptr) : 100;

    float4 e4[2]  = { E0[i],    E0[i + stride] };
    float4 i4[2]  = { I0[i],    I0[i + stride] };
    float4 xe4[2] = { IextE[i], IextE[i + stride] };
    float4 xi4[2] = { IextI[i], IextI[i + stride] };

    u64 E2[4], I2[4];
    u64 cE2[4], cI2[4];     // tanh-path constants 0.5*(Iext-4), all 4 pairs
    u64 sE0, sI0;           // exp-path constants  L*(4-Iext), pair 3 only
    {
        const float* e[2]  = { &e4[0].x,  &e4[1].x };
        const float* ii[2] = { &i4[0].x,  &i4[1].x };
        const float* xe[2] = { &xe4[0].x, &xe4[1].x };
        const float* xi[2] = { &xi4[0].x, &xi4[1].x };
        #pragma unroll
        for (int p = 0; p < 4; ++p) {
            int q = p >> 1, h = p & 1;
            E2[p]  = pack2(e[q][2*h],  e[q][2*h+1]);
            I2[p]  = pack2(ii[q][2*h], ii[q][2*h+1]);
            cE2[p] = pack2(0.5f*(xe[q][2*h]-4.0f), 0.5f*(xe[q][2*h+1]-4.0f));
            cI2[p] = pack2(0.5f*(xi[q][2*h]-4.0f), 0.5f*(xi[q][2*h+1]-4.0f));
        }
        sE0 = pack2(LOG2E*(4.0f-xe4[1].z), LOG2E*(4.0f-xe4[1].w));
        sI0 = pack2(LOG2E*(4.0f-xi4[1].z), LOG2E*(4.0f-xi4[1].w));
    }

    // tanh path (y = 0.5*(input-4); E' = 0.99E + 0.005(1+tanh))
    const u64 AEE = pack2( 6.0f,  6.0f);
    const u64 AEI = pack2(-2.0f, -2.0f);
    const u64 AIE = pack2( 6.5f,  6.5f);
    const u64 AII = pack2(-5.5f, -5.5f);
    const u64 ME  = pack2(0.99f, 0.99f);
    const u64 BE  = pack2(0.005f, 0.005f);
    const u64 MI  = pack2(0.98f, 0.98f);
    const u64 BI  = pack2(0.01f, 0.01f);
    // exp path (s = L*(4-input); sigma = 1/(1+2^s); E' = 0.99E + 0.01*sigma)
    const u64 XEE = pack2(-12.0f*LOG2E, -12.0f*LOG2E);
    const u64 XEI = pack2(  4.0f*LOG2E,   4.0f*LOG2E);
    const u64 XIE = pack2(-13.0f*LOG2E, -13.0f*LOG2E);
    const u64 XII = pack2( 11.0f*LOG2E,  11.0f*LOG2E);
    const u64 KE  = pack2(0.01f, 0.01f);
    const u64 KI  = pack2(0.02f, 0.02f);
    const u64 MAG  = pack2(12582912.0f, 12582912.0f);     // 1.5*2^23
    const u64 NEG1 = pack2(-1.0f, -1.0f);
    const u64 ONE  = pack2( 1.0f,  1.0f);
    const u64 TWO  = pack2( 2.0f,  2.0f);
    const u64 A1 = pack2(0.69314718f, 0.69314718f);
    const u64 A2 = pack2(0.24022651f, 0.24022651f);
    const u64 A3 = pack2(0.05550411f, 0.05550411f);
    const u64 A4 = pack2(0.00961813f, 0.00961813f);

    // one tanh-path step for pair p
    auto tanh_step = [&](int p) {
        u64 yE = fma2(AEE, E2[p], fma2(AEI, I2[p], cE2[p]));
        u64 yI = fma2(AIE, E2[p], fma2(AII, I2[p], cI2[p]));
        float a, b, c, d;
        unpack2(a, b, yE);
        unpack2(c, d, yI);
        u64 tE = pack2(tanhf_a(a), tanhf_a(b));
        u64 tI = pack2(tanhf_a(c), tanhf_a(d));
        E2[p] = fma2(BE, tE, fma2(ME, E2[p], BE));
        I2[p] = fma2(BI, tI, fma2(MI, I2[p], BI));
    };

    // packed 2^s: magic-add range reduction + deg-4 Taylor + exponent splice
    auto exp2_2 = [&](u64 s2) -> u64 {
        u64 m2 = add2(s2, MAG);            // low bits hold rint(s)
        u64 d2 = fma2(MAG, NEG1, m2);      // float(rint(s)), exact
        u64 f2 = fma2(d2, NEG1, s2);       // f in [-0.5, 0.5]
        u64 p  = fma2(A4, f2, A3);
        p = fma2(p, f2, A2);
        p = fma2(p, f2, A1);
        p = fma2(p, f2, ONE);
        float mlo, mhi, plo, phi;
        unpack2(mlo, mhi, m2);
        unpack2(plo, phi, p);
        int zlo = __float_as_int(plo) + (__float_as_int(mlo) << 23);
        int zhi = __float_as_int(phi) + (__float_as_int(mhi) << 23);
        return pack2(__int_as_float(zlo), __int_as_float(zhi));
    };

    // one exp-path step for pair 3 (MUFU-free; shared Newton-2 reciprocal,
    // negations via sign-bit XOR on the ALU pipe)
    auto exp_step3 = [&]() {
        u64 sE = fma2(XEE, E2[3], fma2(XEI, I2[3], sE0));
        u64 sI = fma2(XIE, E2[3], fma2(XII, I2[3], sI0));
        u64 zE = exp2_2(sE);
        u64 zI = exp2_2(sI);
        u64 wE = add2(zE, ONE);
        u64 wI = add2(zI, ONE);
        u64 P  = mul2(wE, wI);             // in [1, ~1e10], normal
        float plo, phi;
        unpack2(plo, phi, P);
        u64 r = pack2(__int_as_float(0x7EF311C3 - __float_as_int(plo)),
                      __int_as_float(0x7EF311C3 - __float_as_int(phi)));
        r = mul2(r, fma2(P, r ^ SIGN2, TWO));   // Newton 1: r*(2 - P*r)
        r = mul2(r, fma2(P, r ^ SIGN2, TWO));   // Newton 2: rel err ~1e-6
        u64 gE = mul2(r, wI);              // 1/wE
        u64 gI = mul2(r, wE);              // 1/wI
        E2[3] = fma2(KE, gE, mul2(ME, E2[3]));
        I2[3] = fma2(KI, gI, mul2(MI, I2[3]));
    };

    // 5:1 dither on pair 3 (exp : tanh) -> exp fraction 0.84 for steps=100
    int blocks6 = steps / 6;
    int rem     = steps - blocks6 * 6;
    for (int b = 0; b < blocks6; ++b) {
        #pragma unroll
        for (int k = 0; k < 5; ++k) {
            tanh_step(0); tanh_step(1); tanh_step(2); exp_step3();
        }
        tanh_step(0); tanh_step(1); tanh_step(2); tanh_step(3);
    }
    for (int s = 0; s < rem; ++s) {
        tanh_step(0); tanh_step(1); tanh_step(2); exp_step3();
    }

    #pragma unroll
    for (int q = 0; q < 2; ++q) {
        float4 eo, io;
        unpack2(eo.x, eo.y, E2[q*2]); unpack2(eo.z, eo.w, E2[q*2+1]);
        unpack2(io.x, io.y, I2[q*2]); unpack2(io.z, io.w, I2[q*2+1]);
        eo.x = __saturatef(eo.x); eo.y = __saturatef(eo.y);
        eo.z = __saturatef(eo.z); eo.w = __saturatef(eo.w);
        io.x = __saturatef(io.x); io.y = __saturatef(io.y);
        io.z = __saturatef(io.z); io.w = __saturatef(io.w);
        int idx = i + q * stride;
        reinterpret_cast<float4*>(out)[idx]     = eo;
        reinterpret_cast<float4*>(out + n)[idx] = io;
    }
}

extern "C" void kernel_launch(void* const* d_in, const int* in_sizes, int n_in,
                              void* d_out, int out_size)
{
    const float4* E0    = (const float4*)d_in[0];
    const float4* I0    = (const float4*)d_in[1];
    const float4* IextE = (const float4*)d_in[2];
    const float4* IextI = (const float4*)d_in[3];
    const int* steps_ptr = (n_in >= 5) ? (const int*)d_in[4] : nullptr;

    int n = in_sizes[0];
    int n4 = n / 4;
    int work = n4 / 2;                 // 8 elems per thread
    int threads = 128;
    int blocks = (work + threads - 1) / threads;   // 1024

    wilson_cowan_kernel<<<blocks, threads>>>(E0, I0, IextE, IextI, steps_ptr,
                                             (float*)d_out, n, n4, out_size);
}